// round 3
// baseline (speedup 1.0000x reference)
#include <cuda_runtime.h>

#define NQ 12
#define DIM 4096
#define NTHREADS 256
#define PADDED (DIM + DIM / 16)   // 4352

typedef unsigned long long ull;

// Per-(layer,qubit) ZYZ data:  U = RZ(alpha) RY(theta) RZ(beta)
__device__ float2 g_ry[3][12];            // (cos(theta/2), sin(theta/2))
__device__ float2 g_ab[3][12];            // (alpha, beta)
// Per-layer combined diagonal applied before the layer's RY stage.
__device__ float2 g_diag[3][DIM];

__device__ __forceinline__ float2 cmulc(float2 a, float2 b) {
    return make_float2(a.x * b.x - a.y * b.y, a.x * b.y + a.y * b.x);
}

// Kernel 1: fuse RZ(c)RX(b)RY(a) per (layer,q), then ZYZ-decompose.
__global__ void precompute_U_kernel(const float* __restrict__ params) {
    int i = threadIdx.x;            // 0..35 -> (layer, q)
    if (i >= 36) return;
    int layer = i / 12, q = i % 12;
    const float* p = params + i * 3;   // params[layer][q][{ry,rx,rz}]
    float sa, ca; sincosf(0.5f * p[0], &sa, &ca);
    float sb, cb; sincosf(0.5f * p[1], &sb, &cb);
    float sc, cc; sincosf(0.5f * p[2], &sc, &cc);
    // M = RX(b) * RY(a)
    float2 m00 = make_float2( cb * ca, -sb * sa);
    float2 m10 = make_float2( cb * sa, -sb * ca);
    // U = RZ(c) * M : row0 *= e^{-ic/2}, row1 *= e^{+ic/2}
    float2 e0 = make_float2(cc, -sc);
    float2 e1 = make_float2(cc,  sc);
    float2 u00 = cmulc(e0, m00);
    float2 u10 = cmulc(e1, m10);
    // ZYZ extraction (U is SU(2)):
    //   u00 = e^{-i(alpha+beta)/2} cos(theta/2),  u10 = e^{i(alpha-beta)/2} sin(theta/2)
    float ct = sqrtf(u00.x * u00.x + u00.y * u00.y);
    float st = sqrtf(u10.x * u10.x + u10.y * u10.y);
    float ApB = -2.0f * atan2f(u00.y, u00.x);
    float AmB =  2.0f * atan2f(u10.y, u10.x);
    g_ry[layer][q] = make_float2(ct, st);
    g_ab[layer][q] = make_float2(0.5f * (ApB + AmB), 0.5f * (ApB - AmB));
}

// Kernel 2: build the per-layer combined diagonals.
//   diag[0][n]   = Zbeta_0[n]
//   diag[l][n]   = Zbeta_l[n] * Zalpha_{l-1}[gray(n)]   (l = 1, 2)
// where Z*(wire q) contributes e^{+i*ang/2} if bit(11-q)(idx)=1 else e^{-i*ang/2}.
// (Zalpha_2 and the final permutation provably don't affect outputs 0/1.)
__global__ void precompute_diag_kernel() {
    int i = blockIdx.x * blockDim.x + threadIdx.x;   // 0 .. 3*DIM-1
    if (i >= 3 * DIM) return;
    int l = i >> 12;
    int n = i & (DIM - 1);
    float angle = 0.0f;
#pragma unroll
    for (int q = 0; q < NQ; ++q) {
        float s = ((n >> (11 - q)) & 1) ? 0.5f : -0.5f;
        angle += s * g_ab[l][q].y;               // beta of this layer
    }
    if (l > 0) {
        int gn = n ^ (n >> 1);
#pragma unroll
        for (int q = 0; q < NQ; ++q) {
            float s = ((gn >> (11 - q)) & 1) ? 0.5f : -0.5f;
            angle += s * g_ab[l - 1][q].x;       // alpha of previous layer
        }
    }
    float si, co; sincosf(angle, &si, &co);
    g_diag[l][n] = make_float2(co, si);
}

// ---- packed f32x2 helpers (lane0 = batch b0, lane1 = batch b1) ----
__device__ __forceinline__ ull pack2(float lo, float hi) {
    ull r; asm("mov.b64 %0, {%1, %2};" : "=l"(r) : "f"(lo), "f"(hi)); return r;
}
__device__ __forceinline__ ull bcast2(float v) { return pack2(v, v); }
__device__ __forceinline__ void unpack2(ull v, float& lo, float& hi) {
    asm("mov.b64 {%0, %1}, %2;" : "=f"(lo), "=f"(hi) : "l"(v));
}
__device__ __forceinline__ ull fma2(ull a, ull b, ull c) {
    ull d; asm("fma.rn.f32x2 %0, %1, %2, %3;" : "=l"(d) : "l"(a), "l"(b), "l"(c)); return d;
}
__device__ __forceinline__ ull mul2(ull a, ull b) {
    ull d; asm("mul.rn.f32x2 %0, %1, %2;" : "=l"(d) : "l"(a), "l"(b)); return d;
}

// Padded shared index: +1 slot per 16 to kill stride-16/256 bank conflicts.
__device__ __forceinline__ int padidx(int n) { return n + (n >> 4); }

// Inverse Gray code (prefix XOR), 12 bits.
__device__ __forceinline__ int grayinv(int i) {
    i ^= i >> 1; i ^= i >> 2; i ^= i >> 4; i ^= i >> 8;
    return i;
}

// Apply 4 REAL RY gates (global bits basebit..basebit+3) to the 16 packed
// amplitudes at base + k*stride.
//   LOAD: fetch registers from shared first.
//   DIAG: after load, multiply amp k by complex diag dg[k] (pass-1 only).
//   GRAY: write back through the CNOT-chain permutation.
template<bool LOAD, bool GRAY, bool DIAG>
__device__ __forceinline__ void gate_pass(ull* sre, ull* sim,
                                          const float2* __restrict__ sRYl,
                                          const float2* __restrict__ dg,
                                          int base, int stride, int basebit,
                                          ull* vr, ull* vi)
{
    if (LOAD) {
#pragma unroll
        for (int k = 0; k < 16; ++k) {
            int pn = padidx(base + k * stride);
            vr[k] = sre[pn]; vi[k] = sim[pn];
        }
    }
    if (DIAG) {
#pragma unroll
        for (int k = 0; k < 16; ++k) {
            float2 d = dg[k];
            ull pr = bcast2(d.x), pi = bcast2(d.y), npi = bcast2(-d.y);
            ull ar = vr[k], ai = vi[k];
            vr[k] = fma2(pr, ar, mul2(npi, ai));
            vi[k] = fma2(pr, ai, mul2(pi, ar));
        }
    }
#pragma unroll
    for (int m = 0; m < 4; ++m) {
        // global bit p = basebit + m  <->  wire = 11 - p
        float2 g = sRYl[11 - basebit - m];
        ull c = bcast2(g.x), s = bcast2(g.y), ns = bcast2(-g.y);
#pragma unroll
        for (int k = 0; k < 16; ++k) {
            if (k & (1 << m)) continue;
            int k1 = k | (1 << m);
            ull ar = vr[k], ai = vi[k], br = vr[k1], bi = vi[k1];
            vr[k]  = fma2(c, ar, mul2(ns, br));
            vr[k1] = fma2(c, br, mul2(s,  ar));
            vi[k]  = fma2(c, ai, mul2(ns, bi));
            vi[k1] = fma2(c, bi, mul2(s,  ai));
        }
    }
#pragma unroll
    for (int k = 0; k < 16; ++k) {
        int idx = base + k * stride;
        int j = GRAY ? grayinv(idx) : idx;
        int pn = padidx(j);
        sre[pn] = vr[k]; sim[pn] = vi[k];
    }
}

__global__ __launch_bounds__(NTHREADS, 2)
void qnn_kernel(const float* __restrict__ x, float* __restrict__ out, int B)
{
    extern __shared__ ull smembuf[];
    ull* sre = smembuf;            // PADDED packed re
    ull* sim = smembuf + PADDED;   // PADDED packed im

    __shared__ float2 sRY[3][12];
    __shared__ ull scw2[NQ], ssw2[NQ];

    const int tid = threadIdx.x;
    const int b0 = 2 * blockIdx.x;
    const int b1 = (b0 + 1 < B) ? b0 + 1 : b0;

    if (tid < NQ) {
        float sa, ca; sincosf(0.5f * x[b0 * NQ + tid], &sa, &ca);
        float sb, cb; sincosf(0.5f * x[b1 * NQ + tid], &sb, &cb);
        scw2[tid] = pack2(ca, cb);
        ssw2[tid] = pack2(sa, sb);
    }
    if (tid < 36) ((float2*)sRY)[tid] = ((const float2*)g_ry)[tid];
    __syncthreads();

    ull vr[16], vi[16];

    // ---- layer 0: build product state in pass-1 layout (idx = tid*16+k),
    // scale by diag0 (makes it complex), run bits 0..3 gates.
    {
        const float2* dg0 = &g_diag[0][tid << 4];
        // idx bits 4..11 come from tid; bit p <-> wire 11-p.
        ull phi = ((tid >> 7) & 1) ? ssw2[0] : scw2[0];
#pragma unroll
        for (int w = 1; w < 8; ++w)
            phi = mul2(phi, ((tid >> (7 - w)) & 1) ? ssw2[w] : scw2[w]);
        ull lo[4], hi[4];
#pragma unroll
        for (int a = 0; a < 4; ++a)
            lo[a] = mul2((a & 1) ? ssw2[11] : scw2[11],
                         (a & 2) ? ssw2[10] : scw2[10]);
#pragma unroll
        for (int bq = 0; bq < 4; ++bq)
            hi[bq] = mul2(phi, mul2((bq & 1) ? ssw2[9] : scw2[9],
                                    (bq & 2) ? ssw2[8] : scw2[8]));
#pragma unroll
        for (int k = 0; k < 16; ++k) {
            ull p = mul2(hi[(k >> 2) & 3], lo[k & 3]);
            float2 d = dg0[k];
            vr[k] = mul2(bcast2(d.x), p);
            vi[k] = mul2(bcast2(d.y), p);
        }
        gate_pass<false, false, false>(sre, sim, sRY[0], nullptr,
                                       tid << 4, 1, 0, vr, vi);
    }
    __syncthreads();
    gate_pass<true, false, false>(sre, sim, sRY[0], nullptr,
                                  (tid & 15) | ((tid >> 4) << 8), 16, 4, vr, vi);
    __syncthreads();
    gate_pass<true, true, false>(sre, sim, sRY[0], nullptr, tid, 256, 8, vr, vi);
    __syncthreads();

#pragma unroll 1
    for (int layer = 1; layer < 3; ++layer) {
        const float2* dg = &g_diag[layer][tid << 4];
        gate_pass<true, false, true >(sre, sim, sRY[layer], dg,
                                      tid << 4, 1, 0, vr, vi);
        __syncthreads();
        gate_pass<true, false, false>(sre, sim, sRY[layer], nullptr,
                                      (tid & 15) | ((tid >> 4) << 8), 16, 4, vr, vi);
        __syncthreads();
        gate_pass<true, true, false>(sre, sim, sRY[layer], nullptr,
                                     tid, 256, 8, vr, vi);
        __syncthreads();
    }

    if (tid == 0) {
        float r0a, r0b, i0a, i0b, r1a, r1b, i1a, i1b;
        unpack2(sre[padidx(0)], r0a, r0b);
        unpack2(sim[padidx(0)], i0a, i0b);
        unpack2(sre[padidx(1)], r1a, r1b);
        unpack2(sim[padidx(1)], i1a, i1b);
        {
            float p0 = r0a * r0a + i0a * i0a;
            float p1 = r1a * r1a + i1a * i1a;
            float inv = 1.0f / (p0 + p1);
            out[b0 * 2 + 0] = p0 * inv;
            out[b0 * 2 + 1] = p1 * inv;
        }
        if (b1 != b0) {
            float p0 = r0b * r0b + i0b * i0b;
            float p1 = r1b * r1b + i1b * i1b;
            float inv = 1.0f / (p0 + p1);
            out[b1 * 2 + 0] = p0 * inv;
            out[b1 * 2 + 1] = p1 * inv;
        }
    }
}

extern "C" void kernel_launch(void* const* d_in, const int* in_sizes, int n_in,
                              void* d_out, int out_size) {
    const float* x      = (const float*)d_in[0];  // (B, 12) float32
    const float* params = (const float*)d_in[1];  // (3, 12, 3) float32
    float* out = (float*)d_out;                   // (B, 2) float32
    int B = in_sizes[0] / NQ;
    int grid = (B + 1) / 2;

    size_t shbytes = 2ull * PADDED * sizeof(ull);   // 69632 bytes
    static bool attr_done = false;
    if (!attr_done) {
        cudaFuncSetAttribute(qnn_kernel,
                             cudaFuncAttributeMaxDynamicSharedMemorySize,
                             (int)shbytes);
        attr_done = true;
    }

    precompute_U_kernel<<<1, 64>>>(params);
    precompute_diag_kernel<<<(3 * DIM + 255) / 256, 256>>>();
    qnn_kernel<<<grid, NTHREADS, shbytes>>>(x, out, B);
}

// round 4
// speedup vs baseline: 11.1289x; 11.1289x over previous
#include <cuda_runtime.h>
#include <math_constants.h>

#define NQ 12
#define DIM 4096
#define NTHREADS 256
#define PADDED (DIM + DIM / 16)   // 4352

typedef unsigned long long ull;

// Packed output-row vectors: g_v[2n] = (Re v0[n], Re v1[n]), g_v[2n+1] = (Im v0, Im v1)
__device__ ull g_v[2 * DIM];

// ---- packed f32x2 helpers ----
__device__ __forceinline__ ull pack2(float lo, float hi) {
    ull r; asm("mov.b64 %0, {%1, %2};" : "=l"(r) : "f"(lo), "f"(hi)); return r;
}
__device__ __forceinline__ ull bcast2(float v) { return pack2(v, v); }
__device__ __forceinline__ void unpack2(ull v, float& lo, float& hi) {
    asm("mov.b64 {%0, %1}, %2;" : "=f"(lo), "=f"(hi) : "l"(v));
}
__device__ __forceinline__ ull fma2(ull a, ull b, ull c) {
    ull d; asm("fma.rn.f32x2 %0, %1, %2, %3;" : "=l"(d) : "l"(a), "l"(b), "l"(c)); return d;
}
__device__ __forceinline__ ull mul2(ull a, ull b) {
    ull d; asm("mul.rn.f32x2 %0, %1, %2;" : "=l"(d) : "l"(a), "l"(b)); return d;
}
__device__ __forceinline__ ull add2(ull a, ull b) {
    ull d; asm("add.rn.f32x2 %0, %1, %2;" : "=l"(d) : "l"(a), "l"(b)); return d;
}

__device__ __forceinline__ int padidx(int n) { return n + (n >> 4); }

// Inverse Gray code (prefix XOR), 12 bits.
__device__ __forceinline__ int grayinv(int i) {
    i ^= i >> 1; i ^= i >> 2; i ^= i >> 4; i ^= i >> 8;
    return i;
}

__device__ __forceinline__ float2 cmulc(float2 a, float2 b) {
    return make_float2(a.x * b.x - a.y * b.y, a.x * b.y + a.y * b.x);
}

// Complex gate pass: 4 gates on global bits basebit..basebit+3.
// LOADMODE: 0 = registers already hold data, 1 = plain load, 2 = grayinv-gather load.
template<int LOADMODE>
__device__ __forceinline__ void cgate_pass(ull* sre, ull* sim,
                                           const float2 (*sUl)[4],
                                           int base, int stride, int basebit,
                                           ull* vr, ull* vi)
{
    if (LOADMODE == 1) {
#pragma unroll
        for (int k = 0; k < 16; ++k) {
            int pn = padidx(base + k * stride);
            vr[k] = sre[pn]; vi[k] = sim[pn];
        }
    } else if (LOADMODE == 2) {
#pragma unroll
        for (int k = 0; k < 16; ++k) {
            int pn = padidx(grayinv(base + k * stride));
            vr[k] = sre[pn]; vi[k] = sim[pn];
        }
    }
#pragma unroll
    for (int m = 0; m < 4; ++m) {
        const float2* u = sUl[11 - basebit - m];   // bit p <-> wire 11-p
        float2 u0 = u[0], u1 = u[1], u2 = u[2], u3 = u[3];
        ull u00x = bcast2(u0.x), u00y = bcast2(u0.y), n00y = bcast2(-u0.y);
        ull u01x = bcast2(u1.x), u01y = bcast2(u1.y), n01y = bcast2(-u1.y);
        ull u10x = bcast2(u2.x), u10y = bcast2(u2.y), n10y = bcast2(-u2.y);
        ull u11x = bcast2(u3.x), u11y = bcast2(u3.y), n11y = bcast2(-u3.y);
#pragma unroll
        for (int k = 0; k < 16; ++k) {
            if (k & (1 << m)) continue;
            int k1 = k | (1 << m);
            ull ar = vr[k], ai = vi[k], br = vr[k1], bi = vi[k1];
            vr[k]  = fma2(u00x, ar, fma2(n00y, ai, fma2(u01x, br, mul2(n01y, bi))));
            vi[k]  = fma2(u00x, ai, fma2(u00y, ar, fma2(u01x, bi, mul2(u01y, br))));
            vr[k1] = fma2(u10x, ar, fma2(n10y, ai, fma2(u11x, br, mul2(n11y, bi))));
            vi[k1] = fma2(u10x, ai, fma2(u10y, ar, fma2(u11x, bi, mul2(u11y, br))));
        }
    }
#pragma unroll
    for (int k = 0; k < 16; ++k) {
        int pn = padidx(base + k * stride);
        sre[pn] = vr[k]; sim[pn] = vi[k];
    }
}

// Setup: compute v_j = conj(U_fixed^dagger |j>) for j=0,1 packed in f32x2 lanes.
// U_fixed = Layer0 -> Layer1 -> Layer2, Layer = (12 fused gates, then CNOT chain).
// Adjoint: for layer 2,1,0: apply P^dagger (grayinv gather) then adjoint gates.
__global__ __launch_bounds__(NTHREADS)
void setup_kernel(const float* __restrict__ params)
{
    extern __shared__ ull smembuf[];
    ull* sre = smembuf;
    ull* sim = smembuf + PADDED;
    __shared__ float2 sU[3][12][4];   // ADJOINT matrices

    const int tid = threadIdx.x;

    if (tid < 36) {
        int layer = tid / 12, q = tid % 12;
        const float* p = params + tid * 3;
        float sa, ca; sincosf(0.5f * p[0], &sa, &ca);
        float sb, cb; sincosf(0.5f * p[1], &sb, &cb);
        float sc, cc; sincosf(0.5f * p[2], &sc, &cc);
        float2 m00 = make_float2( cb * ca, -sb * sa);
        float2 m01 = make_float2(-cb * sa, -sb * ca);
        float2 m10 = make_float2( cb * sa, -sb * ca);
        float2 m11 = make_float2( cb * ca,  sb * sa);
        float2 e0 = make_float2(cc, -sc);
        float2 e1 = make_float2(cc,  sc);
        float2 u00 = cmulc(e0, m00);
        float2 u01 = cmulc(e0, m01);
        float2 u10 = cmulc(e1, m10);
        float2 u11 = cmulc(e1, m11);
        // adjoint = conj-transpose
        sU[layer][q][0] = make_float2(u00.x, -u00.y);
        sU[layer][q][1] = make_float2(u10.x, -u10.y);
        sU[layer][q][2] = make_float2(u01.x, -u01.y);
        sU[layer][q][3] = make_float2(u11.x, -u11.y);
    }
    __syncthreads();

    ull vr[16], vi[16];

    // ---- layer 2 adjoint. P^dagger fixes e0, e1 (grayinv(0)=0, grayinv(1)=1),
    // so init directly in pass-1 register layout (idx = tid*16 + k).
#pragma unroll
    for (int k = 0; k < 16; ++k) { vr[k] = 0ULL; vi[k] = 0ULL; }
    if (tid == 0) {
        vr[0] = pack2(1.0f, 0.0f);   // lane0 = |0>, lane1 = |1>
        vr[1] = pack2(0.0f, 1.0f);
    }
    cgate_pass<0>(sre, sim, sU[2], tid << 4, 1, 0, vr, vi);
    __syncthreads();
    cgate_pass<1>(sre, sim, sU[2], (tid & 15) | ((tid >> 4) << 8), 16, 4, vr, vi);
    __syncthreads();
    cgate_pass<1>(sre, sim, sU[2], tid, 256, 8, vr, vi);
    __syncthreads();

#pragma unroll 1
    for (int layer = 1; layer >= 0; --layer) {
        cgate_pass<2>(sre, sim, sU[layer], tid << 4, 1, 0, vr, vi);
        __syncthreads();
        cgate_pass<1>(sre, sim, sU[layer], (tid & 15) | ((tid >> 4) << 8), 16, 4, vr, vi);
        __syncthreads();
        cgate_pass<1>(sre, sim, sU[layer], tid, 256, 8, vr, vi);
        __syncthreads();
    }

    // v = conj(state): negate imaginary part, write interleaved (re, im).
    const ull signmask = 0x8000000080000000ULL;
    for (int i = tid; i < DIM; i += NTHREADS) {
        g_v[2 * i + 0] = sre[padidx(i)];
        g_v[2 * i + 1] = sim[padidx(i)] ^ signmask;
    }
}

// Main: amp_j(b) = sum_n v_j[n] * psi0_b[n], psi0 = real product state from RY(x).
// n = hi*64 + lo. Warp handles hi in [warpid*8, warpid*8+8) for 32 elements (lanes).
__global__ __launch_bounds__(NTHREADS, 2)
void contract_kernel(const float* __restrict__ x, float* __restrict__ out, int B)
{
    extern __shared__ ull sv[];                 // [DIM][2] interleaved (re, im)
    __shared__ ull partials[8][32][2];          // per-warp partial amps

    const int tid = threadIdx.x;
    const int lane = tid & 31;
    const int warpid = tid >> 5;

    // Load v into shared (coalesced 16B per thread-iteration).
    {
        const ulonglong2* gv = (const ulonglong2*)g_v;
        ulonglong2* svv = (ulonglong2*)sv;
        for (int i = tid; i < DIM; i += NTHREADS) svv[i] = gv[i];
    }

    int b = blockIdx.x * 32 + lane;
    int bb = (b < B) ? b : (B - 1);

    // Per-wire factors f[w] = (cos(x/2), sin(x/2)); bit p of n <-> wire 11-p.
    float fc[NQ], fs[NQ];
#pragma unroll
    for (int w = 0; w < NQ; ++w) {
        float s, c; __sincosf(0.5f * x[bb * NQ + w], &s, &c);
        fc[w] = c; fs[w] = s;
    }
    // A over lo bits 3..5 (wires 8,7,6); Bt over lo bits 0..2 (wires 11,10,9).
    ull a2[8], b2[8];
#pragma unroll
    for (int i = 0; i < 8; ++i) {
        float av = ((i & 1) ? fs[8] : fc[8]) *
                   ((i & 2) ? fs[7] : fc[7]) *
                   ((i & 4) ? fs[6] : fc[6]);
        float bv = ((i & 1) ? fs[11] : fc[11]) *
                   ((i & 2) ? fs[10] : fc[10]) *
                   ((i & 4) ? fs[9]  : fc[9]);
        a2[i] = bcast2(av);
        b2[i] = bcast2(bv);
    }
    // hh over hi bits 0..2 (wires 5,4,3); H over hi bits 3..5 = warpid (wires 2,1,0).
    float hh[8];
#pragma unroll
    for (int t = 0; t < 8; ++t)
        hh[t] = ((t & 1) ? fs[5] : fc[5]) *
                ((t & 2) ? fs[4] : fc[4]) *
                ((t & 4) ? fs[3] : fc[3]);
    float H = ((warpid & 1) ? fs[2] : fc[2]) *
              ((warpid & 2) ? fs[1] : fc[1]) *
              ((warpid & 4) ? fs[0] : fc[0]);

    __syncthreads();

    // inner[t] = sum_lo v[(warpid*8+t)*64 + lo] * A*Bt
    ull ir[8], ii[8];
#pragma unroll
    for (int t = 0; t < 8; ++t) { ir[t] = 0ULL; ii[t] = 0ULL; }

    const ulonglong2* vb = (const ulonglong2*)sv + warpid * 512;  // n offset
#pragma unroll
    for (int i = 0; i < 8; ++i) {
#pragma unroll
        for (int j = 0; j < 8; ++j) {
            ull coef = mul2(a2[i], b2[j]);
            int lo = i * 8 + j;
#pragma unroll
            for (int t = 0; t < 8; ++t) {
                ulonglong2 v = vb[t * 64 + lo];   // broadcast across lanes
                ir[t] = fma2(v.x, coef, ir[t]);
                ii[t] = fma2(v.y, coef, ii[t]);
            }
        }
    }

    ull amp_re = 0ULL, amp_im = 0ULL;
#pragma unroll
    for (int t = 0; t < 8; ++t) {
        ull hcoef = bcast2(H * hh[t]);
        amp_re = fma2(hcoef, ir[t], amp_re);
        amp_im = fma2(hcoef, ii[t], amp_im);
    }
    partials[warpid][lane][0] = amp_re;
    partials[warpid][lane][1] = amp_im;
    __syncthreads();

    if (warpid == 0 && b < B) {
        ull re = partials[0][lane][0];
        ull im = partials[0][lane][1];
#pragma unroll
        for (int w = 1; w < 8; ++w) {
            re = add2(re, partials[w][lane][0]);
            im = add2(im, partials[w][lane][1]);
        }
        float r0, r1, i0, i1;
        unpack2(re, r0, r1);
        unpack2(im, i0, i1);
        float p0 = r0 * r0 + i0 * i0;
        float p1 = r1 * r1 + i1 * i1;
        float inv = 1.0f / (p0 + p1);
        ((float2*)out)[b] = make_float2(p0 * inv, p1 * inv);
    }
}

extern "C" void kernel_launch(void* const* d_in, const int* in_sizes, int n_in,
                              void* d_out, int out_size) {
    const float* x      = (const float*)d_in[0];  // (B, 12) float32
    const float* params = (const float*)d_in[1];  // (3, 12, 3) float32
    float* out = (float*)d_out;                   // (B, 2) float32
    int B = in_sizes[0] / NQ;
    int grid = (B + 31) / 32;

    size_t sh_setup = 2ull * PADDED * sizeof(ull);   // 69632 B
    size_t sh_main  = 2ull * DIM * sizeof(ull);      // 65536 B
    static bool attr_done = false;
    if (!attr_done) {
        cudaFuncSetAttribute(setup_kernel,
                             cudaFuncAttributeMaxDynamicSharedMemorySize,
                             (int)sh_setup);
        cudaFuncSetAttribute(contract_kernel,
                             cudaFuncAttributeMaxDynamicSharedMemorySize,
                             (int)sh_main);
        attr_done = true;
    }

    setup_kernel<<<1, NTHREADS, sh_setup>>>(params);
    contract_kernel<<<grid, NTHREADS, sh_main>>>(x, out, B);
}

// round 5
// speedup vs baseline: 11.9385x; 1.0727x over previous
#include <cuda_runtime.h>

#define NQ 12
#define DIM 4096
#define NTHREADS 256
#define PADDED (DIM + DIM / 16)   // 4352

typedef unsigned long long ull;

// Packed output-row vectors: g_v[2n] = (Re v0[n], Re v1[n]), g_v[2n+1] = (Im v0, Im v1)
__device__ ull g_v[2 * DIM];

// ---- packed f32x2 helpers ----
__device__ __forceinline__ ull pack2(float lo, float hi) {
    ull r; asm("mov.b64 %0, {%1, %2};" : "=l"(r) : "f"(lo), "f"(hi)); return r;
}
__device__ __forceinline__ ull bcast2(float v) { return pack2(v, v); }
__device__ __forceinline__ void unpack2(ull v, float& lo, float& hi) {
    asm("mov.b64 {%0, %1}, %2;" : "=f"(lo), "=f"(hi) : "l"(v));
}
__device__ __forceinline__ ull fma2(ull a, ull b, ull c) {
    ull d; asm("fma.rn.f32x2 %0, %1, %2, %3;" : "=l"(d) : "l"(a), "l"(b), "l"(c)); return d;
}
__device__ __forceinline__ ull mul2(ull a, ull b) {
    ull d; asm("mul.rn.f32x2 %0, %1, %2;" : "=l"(d) : "l"(a), "l"(b)); return d;
}
__device__ __forceinline__ ull add2(ull a, ull b) {
    ull d; asm("add.rn.f32x2 %0, %1, %2;" : "=l"(d) : "l"(a), "l"(b)); return d;
}

__device__ __forceinline__ int padidx(int n) { return n + (n >> 4); }

// Inverse Gray code (prefix XOR), 12 bits.
__device__ __forceinline__ int grayinv(int i) {
    i ^= i >> 1; i ^= i >> 2; i ^= i >> 4; i ^= i >> 8;
    return i;
}

__device__ __forceinline__ float2 cmulc(float2 a, float2 b) {
    return make_float2(a.x * b.x - a.y * b.y, a.x * b.y + a.y * b.x);
}
// bit ? e : conj(e)
__device__ __forceinline__ float2 selE(float2 e, int bit) {
    return make_float2(e.x, bit ? e.y : -e.y);
}
// rotate packed complex (r,i) by scalar complex f (broadcast to both lanes)
__device__ __forceinline__ void crot(ull& r, ull& i, float2 f) {
    ull fx = bcast2(f.x), fy = bcast2(f.y), nfy = bcast2(-f.y);
    ull nr = fma2(fx, r, mul2(nfy, i));
    ull ni = fma2(fx, i, mul2(fy, r));
    r = nr; i = ni;
}

// ================= SETUP: v_j = conj(U^dagger |j>) via ZYZ-real passes ======

// 4 real RY-adjoint gates on global bits basebit..basebit+3.
__device__ __forceinline__ void apply4_real(const float* C, const float* S,
                                            int basebit, ull* vr, ull* vi)
{
#pragma unroll
    for (int m = 0; m < 4; ++m) {
        int wire = 11 - basebit - m;
        float c = C[wire], s = S[wire];
        ull c2 = bcast2(c), s2 = bcast2(s), ns2 = bcast2(-s);
#pragma unroll
        for (int k = 0; k < 16; ++k) {
            if (k & (1 << m)) continue;
            int k1 = k | (1 << m);
            ull ar = vr[k], ai = vi[k], br = vr[k1], bi = vi[k1];
            // adjoint RY: a' = c a + s b ; b' = -s a + c b
            vr[k]  = fma2(c2, ar, mul2(s2, br));
            vi[k]  = fma2(c2, ai, mul2(s2, bi));
            vr[k1] = fma2(c2, br, mul2(ns2, ar));
            vi[k1] = fma2(c2, bi, mul2(ns2, ai));
        }
    }
}

__device__ __forceinline__ void load16(const ull* sre, const ull* sim,
                                       int base, int stride, ull* vr, ull* vi) {
#pragma unroll
    for (int k = 0; k < 16; ++k) {
        int pn = padidx(base + k * stride);
        vr[k] = sre[pn]; vi[k] = sim[pn];
    }
}
__device__ __forceinline__ void load16_gray(const ull* sre, const ull* sim,
                                            int base, int stride, ull* vr, ull* vi) {
#pragma unroll
    for (int k = 0; k < 16; ++k) {
        int pn = padidx(grayinv(base + k * stride));
        vr[k] = sre[pn]; vi[k] = sim[pn];
    }
}
__device__ __forceinline__ void store16(ull* sre, ull* sim,
                                        int base, int stride, const ull* vr, const ull* vi) {
#pragma unroll
    for (int k = 0; k < 16; ++k) {
        int pn = padidx(base + k * stride);
        sre[pn] = vr[k]; sim[pn] = vi[k];
    }
}

// Diagonal D^dagger for pass-1 layout (n = tid*16 + k), angles from E[12]
// where E[q] = e^{-i ang_q / 2}. Factor(n) = prod_q (bit_q(n) ? E : conj(E)).
__device__ __forceinline__ void diag_pass1(const float2* E, int tid, ull* vr, ull* vi) {
    // wires 0..7 <-> tid bits 7..0
    float2 tp = selE(E[0], (tid >> 7) & 1);
#pragma unroll
    for (int q = 1; q < 8; ++q)
        tp = cmulc(tp, selE(E[q], (tid >> (7 - q)) & 1));
    float2 kA[4], kB[4];
#pragma unroll
    for (int j = 0; j < 4; ++j) {
        // k bits 1,0 <-> wires 10,11
        kA[j] = cmulc(selE(E[10], (j >> 1) & 1), selE(E[11], j & 1));
        // k bits 3,2 <-> wires 8,9
        kB[j] = cmulc(selE(E[8], (j >> 1) & 1), selE(E[9], j & 1));
    }
#pragma unroll
    for (int k = 0; k < 16; ++k) {
        float2 f = cmulc(tp, cmulc(kB[k >> 2], kA[k & 3]));
        crot(vr[k], vi[k], f);
    }
}

// Diagonal for pass-3 layout (n = tid + k*256).
__device__ __forceinline__ void diag_pass3(const float2* E, int tid, ull* vr, ull* vi) {
    // wires 4..11 <-> tid bits 7..0  (bit of wire q = (tid >> (11-q)) & 1)
    float2 tp = selE(E[4], (tid >> 7) & 1);
#pragma unroll
    for (int q = 5; q < 12; ++q)
        tp = cmulc(tp, selE(E[q], (tid >> (11 - q)) & 1));
    float2 kA[4], kB[4];
#pragma unroll
    for (int j = 0; j < 4; ++j) {
        // k bits 1,0 <-> wires 2,3
        kA[j] = cmulc(selE(E[2], (j >> 1) & 1), selE(E[3], j & 1));
        // k bits 3,2 <-> wires 0,1
        kB[j] = cmulc(selE(E[0], (j >> 1) & 1), selE(E[1], j & 1));
    }
#pragma unroll
    for (int k = 0; k < 16; ++k) {
        float2 f = cmulc(tp, cmulc(kB[k >> 2], kA[k & 3]));
        crot(vr[k], vi[k], f);
    }
}

__global__ __launch_bounds__(NTHREADS)
void setup_kernel(const float* __restrict__ params)
{
    extern __shared__ ull smembuf[];
    ull* sre = smembuf;
    ull* sim = smembuf + PADDED;
    __shared__ float  sC[3][12], sS[3][12];     // cos(th/2), sin(th/2) (forward)
    __shared__ float2 sEA[3][12], sEB[3][12];   // e^{-i alpha/2}, e^{-i beta/2}

    const int tid = threadIdx.x;

    if (tid < 36) {
        int layer = tid / 12, q = tid % 12;
        const float* p = params + tid * 3;
        float sa, ca; sincosf(0.5f * p[0], &sa, &ca);
        float sb, cb; sincosf(0.5f * p[1], &sb, &cb);
        float sc, cc; sincosf(0.5f * p[2], &sc, &cc);
        float2 m00 = make_float2( cb * ca, -sb * sa);
        float2 m10 = make_float2( cb * sa, -sb * ca);
        float2 e0 = make_float2(cc, -sc);
        float2 e1 = make_float2(cc,  sc);
        float2 u00 = cmulc(e0, m00);
        float2 u10 = cmulc(e1, m10);
        // ZYZ: U = RZ(alpha) RY(theta) RZ(beta)
        float ct = sqrtf(u00.x * u00.x + u00.y * u00.y);
        float st = sqrtf(u10.x * u10.x + u10.y * u10.y);
        float ApB = -2.0f * atan2f(u00.y, u00.x);
        float AmB =  2.0f * atan2f(u10.y, u10.x);
        float alpha = 0.5f * (ApB + AmB);
        float beta  = 0.5f * (ApB - AmB);
        sC[layer][q] = ct; sS[layer][q] = st;
        float s2, c2;
        sincosf(0.5f * alpha, &s2, &c2); sEA[layer][q] = make_float2(c2, -s2);
        sincosf(0.5f * beta,  &s2, &c2); sEB[layer][q] = make_float2(c2, -s2);
    }
    __syncthreads();

    ull vr[16], vi[16];
    const int base1 = tid << 4;
    const int base2 = (tid & 15) | ((tid >> 4) << 8);

    // ---- layer 2 adjoint: P^dagger|j> = |j>, init in pass-1 layout ----
#pragma unroll
    for (int k = 0; k < 16; ++k) { vr[k] = 0ULL; vi[k] = 0ULL; }
    if (tid == 0) {
        vr[0] = pack2(1.0f, 0.0f);   // lane0 = |0>, lane1 = |1>
        vr[1] = pack2(0.0f, 1.0f);
    }
    diag_pass1(sEA[2], tid, vr, vi);
    apply4_real(sC[2], sS[2], 0, vr, vi);
    store16(sre, sim, base1, 1, vr, vi);
    __syncthreads();
    load16(sre, sim, base2, 16, vr, vi);
    apply4_real(sC[2], sS[2], 4, vr, vi);
    store16(sre, sim, base2, 16, vr, vi);
    __syncthreads();
    load16(sre, sim, tid, 256, vr, vi);
    apply4_real(sC[2], sS[2], 8, vr, vi);
    diag_pass3(sEB[2], tid, vr, vi);
    store16(sre, sim, tid, 256, vr, vi);
    __syncthreads();

#pragma unroll 1
    for (int layer = 1; layer >= 0; --layer) {
        load16_gray(sre, sim, base1, 1, vr, vi);          // P^dagger
        diag_pass1(sEA[layer], tid, vr, vi);              // D_alpha^dagger
        apply4_real(sC[layer], sS[layer], 0, vr, vi);
        store16(sre, sim, base1, 1, vr, vi);
        __syncthreads();
        load16(sre, sim, base2, 16, vr, vi);
        apply4_real(sC[layer], sS[layer], 4, vr, vi);
        store16(sre, sim, base2, 16, vr, vi);
        __syncthreads();
        load16(sre, sim, tid, 256, vr, vi);
        apply4_real(sC[layer], sS[layer], 8, vr, vi);
        diag_pass3(sEB[layer], tid, vr, vi);              // D_beta^dagger
        store16(sre, sim, tid, 256, vr, vi);
        __syncthreads();
    }

    // v = conj(state)
    const ull signmask = 0x8000000080000000ULL;
    for (int i = tid; i < DIM; i += NTHREADS) {
        g_v[2 * i + 0] = sre[padidx(i)];
        g_v[2 * i + 1] = sim[padidx(i)] ^ signmask;
    }
}

// ================= CONTRACT ================================================
// amp_j(b) = sum_n v_j[n] * psi0_b[n]; n = hi*64 + lo; warp owns 8 hi rows.
__global__ __launch_bounds__(NTHREADS, 3)
void contract_kernel(const float* __restrict__ x, float* __restrict__ out, int B)
{
    extern __shared__ ull sv[];                 // [DIM][2] interleaved (re, im)
    __shared__ ull partials[8][32][2];

    const int tid = threadIdx.x;
    const int lane = tid & 31;
    const int warpid = tid >> 5;

    // Load v into shared (coalesced 16B per thread-iteration).
    {
        const ulonglong2* gv = (const ulonglong2*)g_v;
        ulonglong2* svv = (ulonglong2*)sv;
#pragma unroll
        for (int i = 0; i < 16; ++i) svv[tid + i * NTHREADS] = gv[tid + i * NTHREADS];
    }

    int b = blockIdx.x * 32 + lane;
    int bb = (b < B) ? b : (B - 1);

    float a2f[8], b2f[8], hfac[8];
    {
        float fc[NQ], fs[NQ];
#pragma unroll
        for (int w = 0; w < NQ; ++w) {
            float s, c; __sincosf(0.5f * x[bb * NQ + w], &s, &c);
            fc[w] = c; fs[w] = s;
        }
#pragma unroll
        for (int i = 0; i < 8; ++i) {
            a2f[i] = ((i & 1) ? fs[8] : fc[8]) *
                     ((i & 2) ? fs[7] : fc[7]) *
                     ((i & 4) ? fs[6] : fc[6]);
            b2f[i] = ((i & 1) ? fs[11] : fc[11]) *
                     ((i & 2) ? fs[10] : fc[10]) *
                     ((i & 4) ? fs[9]  : fc[9]);
        }
        float H = ((warpid & 1) ? fs[2] : fc[2]) *
                  ((warpid & 2) ? fs[1] : fc[1]) *
                  ((warpid & 4) ? fs[0] : fc[0]);
#pragma unroll
        for (int t = 0; t < 8; ++t)
            hfac[t] = H * ((t & 1) ? fs[5] : fc[5]) *
                          ((t & 2) ? fs[4] : fc[4]) *
                          ((t & 4) ? fs[3] : fc[3]);
    }
    __syncthreads();

    const ulonglong2* vb = (const ulonglong2*)sv + warpid * 512;
    ull amp_re = 0ULL, amp_im = 0ULL;

#pragma unroll
    for (int g = 0; g < 2; ++g) {
        const ulonglong2* vg = vb + g * 4 * 64;
        ull ir[4], ii[4];
#pragma unroll
        for (int t = 0; t < 4; ++t) { ir[t] = 0ULL; ii[t] = 0ULL; }

        ulonglong2 cur[4], nxt[4];
#pragma unroll
        for (int t = 0; t < 4; ++t) cur[t] = vg[t * 64];

#pragma unroll
        for (int m = 0; m < 64; ++m) {
            ull coef = bcast2(a2f[m >> 3] * b2f[m & 7]);
            if (m < 63) {
#pragma unroll
                for (int t = 0; t < 4; ++t) nxt[t] = vg[t * 64 + m + 1];
            }
#pragma unroll
            for (int t = 0; t < 4; ++t) {
                ir[t] = fma2(cur[t].x, coef, ir[t]);
                ii[t] = fma2(cur[t].y, coef, ii[t]);
            }
#pragma unroll
            for (int t = 0; t < 4; ++t) cur[t] = nxt[t];
        }
#pragma unroll
        for (int t = 0; t < 4; ++t) {
            ull hc = bcast2(hfac[g * 4 + t]);
            amp_re = fma2(hc, ir[t], amp_re);
            amp_im = fma2(hc, ii[t], amp_im);
        }
    }

    partials[warpid][lane][0] = amp_re;
    partials[warpid][lane][1] = amp_im;
    __syncthreads();

    if (warpid == 0 && b < B) {
        ull re = partials[0][lane][0];
        ull im = partials[0][lane][1];
#pragma unroll
        for (int w = 1; w < 8; ++w) {
            re = add2(re, partials[w][lane][0]);
            im = add2(im, partials[w][lane][1]);
        }
        float r0, r1, i0, i1;
        unpack2(re, r0, r1);
        unpack2(im, i0, i1);
        float p0 = r0 * r0 + i0 * i0;
        float p1 = r1 * r1 + i1 * i1;
        float inv = 1.0f / (p0 + p1);
        ((float2*)out)[b] = make_float2(p0 * inv, p1 * inv);
    }
}

extern "C" void kernel_launch(void* const* d_in, const int* in_sizes, int n_in,
                              void* d_out, int out_size) {
    const float* x      = (const float*)d_in[0];  // (B, 12) float32
    const float* params = (const float*)d_in[1];  // (3, 12, 3) float32
    float* out = (float*)d_out;                   // (B, 2) float32
    int B = in_sizes[0] / NQ;
    int grid = (B + 31) / 32;

    size_t sh_setup = 2ull * PADDED * sizeof(ull);   // 69632 B
    size_t sh_main  = 2ull * DIM * sizeof(ull);      // 65536 B
    static bool attr_done = false;
    if (!attr_done) {
        cudaFuncSetAttribute(setup_kernel,
                             cudaFuncAttributeMaxDynamicSharedMemorySize,
                             (int)sh_setup);
        cudaFuncSetAttribute(contract_kernel,
                             cudaFuncAttributeMaxDynamicSharedMemorySize,
                             (int)sh_main);
        attr_done = true;
    }

    setup_kernel<<<1, NTHREADS, sh_setup>>>(params);
    contract_kernel<<<grid, NTHREADS, sh_main>>>(x, out, B);
}

// round 6
// speedup vs baseline: 12.8609x; 1.0773x over previous
#include <cuda_runtime.h>

#define NQ 12
#define DIM 4096
#define NTHREADS 256
#define PADDED (DIM + DIM / 16)   // 4352

typedef unsigned long long ull;

// Row vectors v_j[n] = <j|U|n>, packed lanes (j=0, j=1): (re, im) per n.
__device__ ulonglong2 g_v2[DIM];
// Split-K partial amplitudes: [half][group][lane] -> (re, im) packed.
__device__ ulonglong2 g_part[2][256][32];

// ---- packed f32x2 helpers ----
__device__ __forceinline__ ull pack2(float lo, float hi) {
    ull r; asm("mov.b64 %0, {%1, %2};" : "=l"(r) : "f"(lo), "f"(hi)); return r;
}
__device__ __forceinline__ ull bcast2(float v) { return pack2(v, v); }
__device__ __forceinline__ void unpack2(ull v, float& lo, float& hi) {
    asm("mov.b64 {%0, %1}, %2;" : "=f"(lo), "=f"(hi) : "l"(v));
}
__device__ __forceinline__ ull fma2(ull a, ull b, ull c) {
    ull d; asm("fma.rn.f32x2 %0, %1, %2, %3;" : "=l"(d) : "l"(a), "l"(b), "l"(c)); return d;
}
__device__ __forceinline__ ull mul2(ull a, ull b) {
    ull d; asm("mul.rn.f32x2 %0, %1, %2;" : "=l"(d) : "l"(a), "l"(b)); return d;
}
__device__ __forceinline__ ull add2(ull a, ull b) {
    ull d; asm("add.rn.f32x2 %0, %1, %2;" : "=l"(d) : "l"(a), "l"(b)); return d;
}

__device__ __forceinline__ int padidx(int n) { return n + (n >> 4); }

// 12-bit inverse Gray code (prefix XOR).
__device__ __forceinline__ int grayinv(int i) {
    i ^= i >> 1; i ^= i >> 2; i ^= i >> 4; i ^= i >> 8;
    return i;
}

__device__ __forceinline__ float2 cmulc(float2 a, float2 b) {
    return make_float2(a.x * b.x - a.y * b.y, a.x * b.y + a.y * b.x);
}
// bit ? e : conj(e)
__device__ __forceinline__ float2 selE(float2 e, int bit) {
    return make_float2(e.x, bit ? e.y : -e.y);
}
// rotate packed complex (r,i) by scalar complex f
__device__ __forceinline__ void crot(ull& r, ull& i, float2 f) {
    ull fx = bcast2(f.x), fy = bcast2(f.y), nfy = bcast2(-f.y);
    ull nr = fma2(fx, r, mul2(nfy, i));
    ull ni = fma2(fx, i, mul2(fy, r));
    r = nr; i = ni;
}

// ====================== SETUP: v = rows <j|U =================================
// Row form: v <- v * L per layer, L = P * (D_alpha RY D_beta).
// Row x RY(theta) pair transform: a' = c a + s b ; b' = -s a + c b.
__device__ __forceinline__ void apply4_real(const float* C, const float* S,
                                            int basebit, ull* vr, ull* vi)
{
#pragma unroll
    for (int m = 0; m < 4; ++m) {
        int wire = 11 - basebit - m;
        float c = C[wire], s = S[wire];
        ull c2 = bcast2(c), s2 = bcast2(s), ns2 = bcast2(-s);
#pragma unroll
        for (int k = 0; k < 16; ++k) {
            if (k & (1 << m)) continue;
            int k1 = k | (1 << m);
            ull ar = vr[k], ai = vi[k], br = vr[k1], bi = vi[k1];
            vr[k]  = fma2(c2, ar, mul2(s2, br));
            vi[k]  = fma2(c2, ai, mul2(s2, bi));
            vr[k1] = fma2(c2, br, mul2(ns2, ar));
            vi[k1] = fma2(c2, bi, mul2(ns2, ai));
        }
    }
}

__device__ __forceinline__ void load16(const ull* sre, const ull* sim,
                                       int base, int stride, ull* vr, ull* vi) {
#pragma unroll
    for (int k = 0; k < 16; ++k) {
        int pn = padidx(base + k * stride);
        vr[k] = sre[pn]; vi[k] = sim[pn];
    }
}
__device__ __forceinline__ void load16_gray(const ull* sre, const ull* sim,
                                            int base, int stride, ull* vr, ull* vi) {
#pragma unroll
    for (int k = 0; k < 16; ++k) {
        int pn = padidx(grayinv(base + k * stride));
        vr[k] = sre[pn]; vi[k] = sim[pn];
    }
}
__device__ __forceinline__ void store16(ull* sre, ull* sim,
                                        int base, int stride, const ull* vr, const ull* vi) {
#pragma unroll
    for (int k = 0; k < 16; ++k) {
        int pn = padidx(base + k * stride);
        sre[pn] = vr[k]; sim[pn] = vi[k];
    }
}

// Diagonal (forward) for pass-1 layout (n = tid*16 + k); E[q] = e^{+i ang_q/2},
// factor(n) = prod_q (bit_q ? E : conj(E)), wire q <-> n bit 11-q.
__device__ __forceinline__ void diag_pass1(const float2* E, int tid, ull* vr, ull* vi) {
    float2 tp = selE(E[0], (tid >> 7) & 1);
#pragma unroll
    for (int q = 1; q < 8; ++q)
        tp = cmulc(tp, selE(E[q], (tid >> (7 - q)) & 1));
    float2 kA[4], kB[4];
#pragma unroll
    for (int j = 0; j < 4; ++j) {
        kA[j] = cmulc(selE(E[10], (j >> 1) & 1), selE(E[11], j & 1));
        kB[j] = cmulc(selE(E[8], (j >> 1) & 1), selE(E[9], j & 1));
    }
#pragma unroll
    for (int k = 0; k < 16; ++k) {
        float2 f = cmulc(tp, cmulc(kB[k >> 2], kA[k & 3]));
        crot(vr[k], vi[k], f);
    }
}

// Diagonal (forward) for pass-3 layout (n = tid + k*256).
__device__ __forceinline__ void diag_pass3(const float2* E, int tid, ull* vr, ull* vi) {
    float2 tp = selE(E[4], (tid >> 7) & 1);
#pragma unroll
    for (int q = 5; q < 12; ++q)
        tp = cmulc(tp, selE(E[q], (tid >> (11 - q)) & 1));
    float2 kA[4], kB[4];
#pragma unroll
    for (int j = 0; j < 4; ++j) {
        kA[j] = cmulc(selE(E[2], (j >> 1) & 1), selE(E[3], j & 1));
        kB[j] = cmulc(selE(E[0], (j >> 1) & 1), selE(E[1], j & 1));
    }
#pragma unroll
    for (int k = 0; k < 16; ++k) {
        float2 f = cmulc(tp, cmulc(kB[k >> 2], kA[k & 3]));
        crot(vr[k], vi[k], f);
    }
}

__global__ __launch_bounds__(NTHREADS)
void setup_kernel(const float* __restrict__ params)
{
    extern __shared__ ull smembuf[];
    ull* sre = smembuf;
    ull* sim = smembuf + PADDED;
    __shared__ float  sC[3][12], sS[3][12];     // cos(th/2), sin(th/2)
    __shared__ float2 sEA[3][12], sEB[3][12];   // e^{+i alpha/2}, e^{+i beta/2} (FORWARD)

    const int tid = threadIdx.x;

    if (tid < 36) {
        int layer = tid / 12, q = tid % 12;
        const float* p = params + tid * 3;
        float sa, ca; sincosf(0.5f * p[0], &sa, &ca);
        float sb, cb; sincosf(0.5f * p[1], &sb, &cb);
        float sc, cc; sincosf(0.5f * p[2], &sc, &cc);
        float2 m00 = make_float2( cb * ca, -sb * sa);
        float2 m10 = make_float2( cb * sa, -sb * ca);
        float2 e0 = make_float2(cc, -sc);
        float2 e1 = make_float2(cc,  sc);
        float2 u00 = cmulc(e0, m00);
        float2 u10 = cmulc(e1, m10);
        // ZYZ: U = RZ(alpha) RY(theta) RZ(beta)
        float ct = sqrtf(u00.x * u00.x + u00.y * u00.y);
        float st = sqrtf(u10.x * u10.x + u10.y * u10.y);
        float ApB = -2.0f * atan2f(u00.y, u00.x);
        float AmB =  2.0f * atan2f(u10.y, u10.x);
        float alpha = 0.5f * (ApB + AmB);
        float beta  = 0.5f * (ApB - AmB);
        sC[layer][q] = ct; sS[layer][q] = st;
        float s2, c2;
        sincosf(0.5f * alpha, &s2, &c2); sEA[layer][q] = make_float2(c2, s2);
        sincosf(0.5f * beta,  &s2, &c2); sEB[layer][q] = make_float2(c2, s2);
    }
    __syncthreads();

    ull vr[16], vi[16];
    const int base1 = tid << 4;
    const int base2 = (tid & 15) | ((tid >> 4) << 8);

    // ---- Analytic layer-2 row, evaluated at m = grayinv(idx) (row * P fused),
    // in pass-1 layout idx = tid*16 + k.
    // r2[m] = prod_q ryrow_q(m_q) * dbeta2[m]   (alpha2 = per-j global phase, dropped)
    {
        int pt = __popc(tid) & 1;
        int mh = tid ^ (tid >> 1); mh ^= mh >> 2; mh ^= mh >> 4;  // grayinv8(tid)
        // wires 0..7 from mh bits 7..0 (wire w <-> m bit 11-w = mh bit 7-w)
        float realH = 1.0f;
        float2 cH = make_float2(1.0f, 0.0f);
#pragma unroll
        for (int w = 0; w < 8; ++w) {
            int bit = (mh >> (7 - w)) & 1;
            realH *= bit ? -sS[2][w] : sC[2][w];
            cH = cmulc(cH, selE(sEB[2][w], bit));
        }
        // m bits 2,3 <-> wires 9,8  (fold realH/cH in)
        float realB[4]; float2 cB[4];
#pragma unroll
        for (int j4 = 0; j4 < 4; ++j4) {
            int b2 = j4 & 1, b3 = (j4 >> 1) & 1;
            realB[j4] = realH * (b2 ? -sS[2][9] : sC[2][9])
                              * (b3 ? -sS[2][8] : sC[2][8]);
            cB[j4] = cmulc(cH, cmulc(selE(sEB[2][9], b2), selE(sEB[2][8], b3)));
        }
        // m bits 0,1 <-> wires 11,10 ; wire 11 is j-lane dependent:
        // lane0 (<0|RY) = (c,-s), lane1 (<1|RY) = (s,c)
        ull realA[4]; float2 cA[4];
#pragma unroll
        for (int j2 = 0; j2 < 4; ++j2) {
            int b0 = j2 & 1, b1 = (j2 >> 1) & 1;
            float r10 = b1 ? -sS[2][10] : sC[2][10];
            float l0 = (b0 ? -sS[2][11] : sC[2][11]) * r10;
            float l1 = (b0 ?  sC[2][11] : sS[2][11]) * r10;
            realA[j2] = pack2(l0, l1);
            cA[j2] = cmulc(selE(sEB[2][11], b0), selE(sEB[2][10], b1));
        }
#pragma unroll
        for (int k = 0; k < 16; ++k) {
            int mlo = k ^ (k >> 1); mlo ^= mlo >> 2;       // grayinv4(k)
            mlo = (mlo ^ (pt ? 0xF : 0)) & 0xF;            // fold tid parity
            int j2 = mlo & 3, j4 = mlo >> 2;
            ull rp = mul2(bcast2(realB[j4]), realA[j2]);
            float2 d = cmulc(cB[j4], cA[j2]);
            vr[k] = mul2(rp, bcast2(d.x));
            vi[k] = mul2(rp, bcast2(d.y));
        }
    }

    // ---- layer 1: (already gathered) -> D_alpha1 -> gates -> D_beta1
    diag_pass1(sEA[1], tid, vr, vi);
    apply4_real(sC[1], sS[1], 0, vr, vi);
    store16(sre, sim, base1, 1, vr, vi);
    __syncthreads();
    load16(sre, sim, base2, 16, vr, vi);
    apply4_real(sC[1], sS[1], 4, vr, vi);
    store16(sre, sim, base2, 16, vr, vi);
    __syncthreads();
    load16(sre, sim, tid, 256, vr, vi);
    apply4_real(sC[1], sS[1], 8, vr, vi);
    diag_pass3(sEB[1], tid, vr, vi);
    store16(sre, sim, tid, 256, vr, vi);
    __syncthreads();

    // ---- layer 0: gather P -> D_alpha0 -> gates -> D_beta0 -> write g_v
    load16_gray(sre, sim, base1, 1, vr, vi);
    diag_pass1(sEA[0], tid, vr, vi);
    apply4_real(sC[0], sS[0], 0, vr, vi);
    store16(sre, sim, base1, 1, vr, vi);
    __syncthreads();
    load16(sre, sim, base2, 16, vr, vi);
    apply4_real(sC[0], sS[0], 4, vr, vi);
    store16(sre, sim, base2, 16, vr, vi);
    __syncthreads();
    load16(sre, sim, tid, 256, vr, vi);
    apply4_real(sC[0], sS[0], 8, vr, vi);
    diag_pass3(sEB[0], tid, vr, vi);
#pragma unroll
    for (int k = 0; k < 16; ++k) {
        int n = tid + (k << 8);
        g_v2[n] = make_ulonglong2(vr[k], vi[k]);
    }
}

// ====================== CONTRACT (split-K halves) ============================
// blockIdx: half = bx & 1 (hi rows [half*32, half*32+32)), group = bx >> 1.
// Warp w handles 4 local rows [w*4, w*4+4); lanes = 32 batch elements.
__global__ __launch_bounds__(NTHREADS, 3)
void contract_kernel(const float* __restrict__ x, int B)
{
    __shared__ ulonglong2 sv[2048];          // this half's v slice: [row32][lo64]
    __shared__ ull partials[8][32][2];

    const int tid = threadIdx.x;
    const int lane = tid & 31;
    const int warpid = tid >> 5;
    const int half = blockIdx.x & 1;
    const int group = blockIdx.x >> 1;

    // Load half of v (32KB), coalesced.
#pragma unroll
    for (int i = 0; i < 8; ++i)
        sv[tid + i * NTHREADS] = g_v2[half * 2048 + tid + i * NTHREADS];

    int b = group * 32 + lane;
    int bb = (b < B) ? b : (B - 1);

    ull  b2p[8];
    float a2f[8], hfac[4];
    {
        float fc[NQ], fs[NQ];
#pragma unroll
        for (int w = 0; w < NQ; ++w) {
            float s, c; __sincosf(0.5f * x[bb * NQ + w], &s, &c);
            fc[w] = c; fs[w] = s;
        }
#pragma unroll
        for (int i = 0; i < 8; ++i) {
            a2f[i] = ((i & 1) ? fs[8] : fc[8]) *
                     ((i & 2) ? fs[7] : fc[7]) *
                     ((i & 4) ? fs[6] : fc[6]);
            float bv = ((i & 1) ? fs[11] : fc[11]) *
                       ((i & 2) ? fs[10] : fc[10]) *
                       ((i & 4) ? fs[9]  : fc[9]);
            b2p[i] = bcast2(bv);
        }
#pragma unroll
        for (int t = 0; t < 4; ++t) {
            int row = half * 32 + warpid * 4 + t;   // global hi row, bits 5..0 -> wires 0..5
            hfac[t] = (((row >> 5) & 1) ? fs[0] : fc[0]) *
                      (((row >> 4) & 1) ? fs[1] : fc[1]) *
                      (((row >> 3) & 1) ? fs[2] : fc[2]) *
                      (((row >> 2) & 1) ? fs[3] : fc[3]) *
                      (((row >> 1) & 1) ? fs[4] : fc[4]) *
                      (((row >> 0) & 1) ? fs[5] : fc[5]);
        }
    }
    __syncthreads();

    const ulonglong2* vw = sv + warpid * 4 * 64;
    ull ir[4], ii[4];
#pragma unroll
    for (int t = 0; t < 4; ++t) { ir[t] = 0ULL; ii[t] = 0ULL; }

#pragma unroll
    for (int i = 0; i < 8; ++i) {
        ull tr[4], ti[4];
#pragma unroll
        for (int t = 0; t < 4; ++t) { tr[t] = 0ULL; ti[t] = 0ULL; }
#pragma unroll
        for (int j = 0; j < 8; ++j) {
#pragma unroll
            for (int t = 0; t < 4; ++t) {
                ulonglong2 v = vw[t * 64 + i * 8 + j];   // warp-broadcast LDS
                tr[t] = fma2(v.x, b2p[j], tr[t]);
                ti[t] = fma2(v.y, b2p[j], ti[t]);
            }
        }
        ull ai = bcast2(a2f[i]);
#pragma unroll
        for (int t = 0; t < 4; ++t) {
            ir[t] = fma2(ai, tr[t], ir[t]);
            ii[t] = fma2(ai, ti[t], ii[t]);
        }
    }

    ull amp_re = 0ULL, amp_im = 0ULL;
#pragma unroll
    for (int t = 0; t < 4; ++t) {
        ull hc = bcast2(hfac[t]);
        amp_re = fma2(hc, ir[t], amp_re);
        amp_im = fma2(hc, ii[t], amp_im);
    }
    partials[warpid][lane][0] = amp_re;
    partials[warpid][lane][1] = amp_im;
    __syncthreads();

    if (warpid == 0) {
        ull re = partials[0][lane][0];
        ull im = partials[0][lane][1];
#pragma unroll
        for (int w = 1; w < 8; ++w) {
            re = add2(re, partials[w][lane][0]);
            im = add2(im, partials[w][lane][1]);
        }
        g_part[half][group][lane] = make_ulonglong2(re, im);
    }
}

// ====================== COMBINE ==============================================
__global__ __launch_bounds__(NTHREADS)
void combine_kernel(float* __restrict__ out, int B)
{
    int b = blockIdx.x * NTHREADS + threadIdx.x;
    if (b >= B) return;
    int group = b >> 5, lane = b & 31;
    ulonglong2 p0 = g_part[0][group][lane];
    ulonglong2 p1 = g_part[1][group][lane];
    ull re = add2(p0.x, p1.x);
    ull im = add2(p0.y, p1.y);
    float r0, r1, i0, i1;
    unpack2(re, r0, r1);
    unpack2(im, i0, i1);
    float q0 = r0 * r0 + i0 * i0;
    float q1 = r1 * r1 + i1 * i1;
    float inv = 1.0f / (q0 + q1);
    ((float2*)out)[b] = make_float2(q0 * inv, q1 * inv);
}

extern "C" void kernel_launch(void* const* d_in, const int* in_sizes, int n_in,
                              void* d_out, int out_size) {
    const float* x      = (const float*)d_in[0];  // (B, 12) float32
    const float* params = (const float*)d_in[1];  // (3, 12, 3) float32
    float* out = (float*)d_out;                   // (B, 2) float32
    int B = in_sizes[0] / NQ;
    int groups = (B + 31) / 32;

    size_t sh_setup = 2ull * PADDED * sizeof(ull);   // 69632 B
    static bool attr_done = false;
    if (!attr_done) {
        cudaFuncSetAttribute(setup_kernel,
                             cudaFuncAttributeMaxDynamicSharedMemorySize,
                             (int)sh_setup);
        attr_done = true;
    }

    setup_kernel<<<1, NTHREADS, sh_setup>>>(params);
    contract_kernel<<<groups * 2, NTHREADS>>>(x, B);
    combine_kernel<<<(B + NTHREADS - 1) / NTHREADS, NTHREADS>>>(out, B);
}